// round 13
// baseline (speedup 1.0000x reference)
#include <cuda_runtime.h>
#include <cuda.h>
#include <cuda_fp16.h>
#include <cstdint>
#include <cstddef>

// ---------------- problem constants ----------------
#define M_TOT 8192
#define DIN   4096
#define DOUT  4096
#define RANK  1024

#define NPAIRS 74
#define GRID_CTAS 148
#define MB 32                  // M_TOT / 256

// ===== GEMM1 layout (R12-proven): pair tile 256x512, BK=128, NSTAGE=2 =====
#define G1_TN 512
#define G1_BK 128
#define G1_NST 2
#define G1_A_STAGE 32768
#define G1_B_STAGE 65536
#define G1_A_OFF 1024
#define G1_B_OFF (G1_A_OFF + G1_NST * G1_A_STAGE)          // 66560
#define G1_SMEM  (G1_B_OFF + G1_NST * G1_B_STAGE)          // 197632

// ===== GEMM2 layout (tall tiles 512x256, BK=128, NSTAGE=2, stage=96KB) =====
#define G2_BK 128
#define G2_NST 2
#define G2_STAGE 98304          // A0 32K | A1 32K | B 32K
#define G2_OFF 1024
#define G2_SMEM (G2_OFF + G2_NST * G2_STAGE)               // 197632
#define G2_MB 16                // M_TOT / 512
#define G2_NB 16                // DOUT / 256

// control block (first 1KB of smem)
#define OFF_TMEM   0
#define OFF_EMPTY  16
#define OFF_PFULL  48
#define OFF_DONE0  80
#define OFF_DONE1  88
#define OFF_EPI0   96
#define OFF_EPI1   104

// idesc: kind::f16, D=f32(bit4), A=F16(0), B=F16(0), N=256, M=256 (cg2)
#define IDESC_F16_CG2 ((1u << 4) | ((256u / 8u) << 17) | ((256u / 16u) << 24))

#define DESC_BASE_SW128 \
    ((uint64_t(2) << 61) | (uint64_t(1) << 46) | (uint64_t(64) << 32) | (uint64_t(1) << 16))

#if defined(__CUDA_ARCH__) && (defined(__CUDA_ARCH_FEAT_SM103_ALL) || defined(__CUDA_ARCH_FEAT_SM100_ALL) || defined(__CUDA_ARCH_FEAT_SM101_ALL))
#define TC_PATH 1
#else
#define TC_PATH 0
#endif

// ---------------- scratch (allocation-free) ----------------
__device__ __align__(16) __half g_W1[(size_t)RANK  * DIN];
__device__ __align__(16) __half g_W2[(size_t)DOUT  * RANK];
__device__ __align__(16) __half g_T [(size_t)M_TOT * RANK];

// ---------------- helpers ----------------
__device__ __forceinline__ uint32_t pack_h2(float lo, float hi) {
    __half2 h = __floats2half2_rn(lo, hi);
    return *reinterpret_cast<uint32_t*>(&h);
}
__device__ __forceinline__ uint32_t smem_u32(const void* p) {
    uint32_t a;
    asm("{ .reg .u64 t; cvta.to.shared.u64 t, %1; cvt.u32.u64 %0, t; }" : "=r"(a) : "l"(p));
    return a;
}
__device__ __forceinline__ uint32_t sw128(uint32_t o) { return o ^ ((o >> 3) & 0x70); }
__device__ __forceinline__ uint32_t cluster_rank() {
    uint32_t r;
    asm("mov.u32 %0, %%cluster_ctarank;" : "=r"(r));
    return r;
}

#if TC_PATH
__device__ __forceinline__ void mbar_init(uint32_t a, uint32_t cnt) {
    asm volatile("mbarrier.init.shared.b64 [%0], %1;" :: "r"(a), "r"(cnt) : "memory");
}
__device__ __forceinline__ void mbar_arrive_rank(uint32_t a, uint32_t rank) {
    asm volatile(
        "{\n\t"
        ".reg .b32 r;\n\t"
        "mapa.shared::cluster.u32 r, %0, %1;\n\t"
        "mbarrier.arrive.shared::cluster.b64 _, [r];\n\t"
        "}" :: "r"(a), "r"(rank) : "memory");
}
__device__ __forceinline__ void mbar_expect_tx(uint32_t a, uint32_t bytes) {
    asm volatile("mbarrier.arrive.expect_tx.shared.b64 _, [%0], %1;"
                 :: "r"(a), "r"(bytes) : "memory");
}
__device__ __forceinline__ void mbar_wait(uint32_t a, uint32_t parity) {
    asm volatile(
        "{\n\t"
        ".reg .pred P;\n\t"
        "W_%=:\n\t"
        "mbarrier.try_wait.parity.acquire.cluster.shared::cta.b64 P, [%0], %1, 0x989680;\n\t"
        "@!P bra.uni W_%=;\n\t"
        "}" :: "r"(a), "r"(parity) : "memory");
}
// cta_group::2 TMA: data to LOCAL smem, complete_tx to the PAIR LEADER's barrier.
__device__ __forceinline__ void tma_ld_2d_cg2(uint32_t dst, const CUtensorMap* m,
                                              int x, int y, uint32_t bar) {
    asm volatile(
        "{\n\t"
        ".reg .b32 lb;\n\t"
        "and.b32 lb, %4, 0xFEFFFFFF;\n\t"
        "cp.async.bulk.tensor.2d.cta_group::2.shared::cluster.global"
        ".tile.mbarrier::complete_tx::bytes [%0], [%1, {%2, %3}], [lb];\n\t"
        "}"
        :: "r"(dst), "l"(m), "r"(x), "r"(y), "r"(bar) : "memory");
}
__device__ __forceinline__ void mma_f16_cg2(uint32_t d_tmem, uint64_t a_desc, uint64_t b_desc,
                                            uint32_t enable_d) {
    asm volatile(
        "{\n\t"
        ".reg .pred p;\n\t"
        "setp.ne.u32 p, %4, 0;\n\t"
        "tcgen05.mma.cta_group::2.kind::f16 [%0], %1, %2, %3, "
        "{%5,%5,%5,%5,%5,%5,%5,%5}, p;\n\t"
        "}"
        :: "r"(d_tmem), "l"(a_desc), "l"(b_desc), "r"(IDESC_F16_CG2), "r"(enable_d), "r"(0u)
        : "memory");
}
__device__ __forceinline__ void tc_commit_mc(uint32_t mbar, uint16_t mask) {
    asm volatile(
        "tcgen05.commit.cta_group::2.mbarrier::arrive::one.shared::cluster.multicast::cluster.b64 [%0], %1;"
        :: "r"(mbar), "h"(mask) : "memory");
}
__device__ __forceinline__ void ldtm_x32(uint32_t* r, uint32_t addr) {
    asm volatile(
        "tcgen05.ld.sync.aligned.32x32b.x32.b32 "
        "{%0, %1, %2, %3, %4, %5, %6, %7, "
        " %8, %9, %10, %11, %12, %13, %14, %15, "
        " %16, %17, %18, %19, %20, %21, %22, %23, "
        " %24, %25, %26, %27, %28, %29, %30, %31}, [%32];"
        : "=r"(r[0]),  "=r"(r[1]),  "=r"(r[2]),  "=r"(r[3]),
          "=r"(r[4]),  "=r"(r[5]),  "=r"(r[6]),  "=r"(r[7]),
          "=r"(r[8]),  "=r"(r[9]),  "=r"(r[10]), "=r"(r[11]),
          "=r"(r[12]), "=r"(r[13]), "=r"(r[14]), "=r"(r[15]),
          "=r"(r[16]), "=r"(r[17]), "=r"(r[18]), "=r"(r[19]),
          "=r"(r[20]), "=r"(r[21]), "=r"(r[22]), "=r"(r[23]),
          "=r"(r[24]), "=r"(r[25]), "=r"(r[26]), "=r"(r[27]),
          "=r"(r[28]), "=r"(r[29]), "=r"(r[30]), "=r"(r[31])
        : "r"(addr));
}
#define TC_WAIT_LD() asm volatile("tcgen05.wait::ld.sync.aligned;" ::: "memory")
#define TC_FENCE_AFTER()  asm volatile("tcgen05.fence::after_thread_sync;" ::: "memory")
#define TC_FENCE_BEFORE() asm volatile("tcgen05.fence::before_thread_sync;" ::: "memory")
#define CLUSTER_SYNC() do { \
    asm volatile("barrier.cluster.arrive.aligned;" ::: "memory"); \
    asm volatile("barrier.cluster.wait.aligned;" ::: "memory"); \
} while (0)
#endif  // TC_PATH

// ---------------- prepass kernels (fp32 -> fp16 rn) ----------------
__global__ void prep_half(const float* __restrict__ in, __half* __restrict__ out, int n4) {
    int i = blockIdx.x * blockDim.x + threadIdx.x;
    int stride = gridDim.x * blockDim.x;
    for (; i < n4; i += stride) {
        float4 v = reinterpret_cast<const float4*>(in)[i];
        uint2 o;
        o.x = pack_h2(v.x, v.y);
        o.y = pack_h2(v.z, v.w);
        reinterpret_cast<uint2*>(out)[i] = o;
    }
}
__global__ void prep_scale_half(const float* __restrict__ Vh, const float* __restrict__ S,
                                __half* __restrict__ out, int cols4) {
    int r = blockIdx.y;
    float s = __ldg(S + r);
    int c = blockIdx.x * blockDim.x + threadIdx.x;
    if (c < cols4) {
        float4 v = reinterpret_cast<const float4*>(Vh + (size_t)r * (cols4 * 4))[c];
        uint2 o;
        o.x = pack_h2(v.x * s, v.y * s);
        o.y = pack_h2(v.z * s, v.w * s);
        reinterpret_cast<uint2*>(out + (size_t)r * (cols4 * 4))[c] = o;
    }
}

// ================= GEMM1 (R12-proven): T = f16(x) @ W1^T, fused rounding =================
__global__ __launch_bounds__(512, 1) __cluster_dims__(2, 1, 1)
void gemm1_f16(const float* __restrict__ Aptr,
               const __grid_constant__ CUtensorMap b_map,
               __half* __restrict__ Dptr, int ntiles)
{
    extern __shared__ char smem[];
    const uint32_t sbase = smem_u32(smem);
    const int tid  = threadIdx.x;
    const int warp = tid >> 5;
    const int lane = tid & 31;
    const uint32_t rank = cluster_rank();
    const int pair = blockIdx.x >> 1;
    const int K = DIN, Nout = RANK, nk = DIN / G1_BK, nbm1 = (RANK / G1_TN) - 1;

#if TC_PATH
    if (warp == 0) {
        asm volatile("tcgen05.alloc.cta_group::2.sync.aligned.shared::cta.b32 [%0], %1;"
                     :: "r"(sbase + OFF_TMEM), "r"(512u) : "memory");
        asm volatile("tcgen05.relinquish_alloc_permit.cta_group::2.sync.aligned;");
    }
    if (tid == 0) {
        #pragma unroll
        for (int s = 0; s < G1_NST; s++) {
            mbar_init(sbase + OFF_EMPTY + 8 * s, 1);
            mbar_init(sbase + OFF_PFULL + 8 * s, 17u);
        }
        mbar_init(sbase + OFF_DONE0, 1);
        mbar_init(sbase + OFF_DONE1, 1);
        mbar_init(sbase + OFF_EPI0, 8);
        mbar_init(sbase + OFF_EPI1, 8);
    }
    __syncthreads();
    CLUSTER_SYNC();

    uint32_t tmem_base;
    asm volatile("ld.shared.b32 %0, [%1];" : "=r"(tmem_base) : "r"(sbase + OFF_TMEM));

    if (warp == 1 && lane == 0) {
        int s = 0, ph = 1;
        for (int t = pair; t < ntiles; t += NPAIRS) {
            const int m = t & (MB - 1), q = t / MB;
            const int nb = (q + (m & nbm1)) & nbm1;
            const int bn = nb * G1_TN;
            for (int kt = 0; kt < nk; kt++) {
                mbar_wait(sbase + OFF_EMPTY + 8 * s, (uint32_t)ph);
                const uint32_t pf = sbase + OFF_PFULL + 8 * s;
                if (rank == 0) mbar_expect_tx(pf, 131072u);
                const uint32_t sB = sbase + G1_B_OFF + s * G1_B_STAGE;
                #pragma unroll
                for (int kh = 0; kh < 2; kh++) {
                    const int x = kt * G1_BK + kh * 64;
                    tma_ld_2d_cg2(sB + kh * 16384,         &b_map, x, bn + (int)rank * 128, pf);
                    tma_ld_2d_cg2(sB + 32768 + kh * 16384, &b_map, x, bn + 256 + (int)rank * 128, pf);
                }
                if (++s == G1_NST) { s = 0; ph ^= 1; }
            }
        }
    } else if (warp >= 8) {
        const int pt = tid - 256;
        int s = 0, ph = 1;
        for (int t = pair; t < ntiles; t += NPAIRS) {
            const int m = t & (MB - 1);
            const int bm_cta = m * 256 + (int)rank * 128;
            const float* Agb = Aptr + (size_t)bm_cta * K;
            for (int kt = 0; kt < nk; kt++) {
                mbar_wait(sbase + OFF_EMPTY + 8 * s, (uint32_t)ph);
                const float* Ag = Agb + (size_t)kt * G1_BK;
                #pragma unroll
                for (int i = 0; i < 8; i++) {
                    int idx = pt + 256 * i;
                    int r = idx >> 4, g = idx & 15;
                    const float* src = Ag + (size_t)r * K + g * 8;
                    float4 p = __ldg(reinterpret_cast<const float4*>(src));
                    float4 w = __ldg(reinterpret_cast<const float4*>(src + 4));
                    uint4 h;
                    h.x = pack_h2(p.x, p.y);
                    h.y = pack_h2(p.z, p.w);
                    h.z = pack_h2(w.x, w.y);
                    h.w = pack_h2(w.z, w.w);
                    uint32_t off = (uint32_t)((g >> 3) * 16384) +
                                   sw128((uint32_t)(r * 128 + (g & 7) * 16));
                    *reinterpret_cast<uint4*>(smem + G1_A_OFF + s * G1_A_STAGE + off) = h;
                }
                asm volatile("fence.proxy.async;" ::: "memory");
                __syncwarp();
                if (lane == 0) mbar_arrive_rank(sbase + OFF_PFULL + 8 * s, 0u);
                if (++s == G1_NST) { s = 0; ph ^= 1; }
            }
        }
    } else if (rank == 0 && warp == 0 && lane == 0) {
        int s = 0, ph = 0, j = 0;
        for (int t = pair; t < ntiles; t += NPAIRS, j++) {
            for (int kt = 0; kt < nk; kt++) {
                mbar_wait(sbase + OFF_PFULL + 8 * s, (uint32_t)ph);
                uint64_t adesc = DESC_BASE_SW128 |
                    (((uint64_t)((sbase + G1_A_OFF + s * G1_A_STAGE) >> 4)) & 0x3FFF);
                uint64_t bdesc = DESC_BASE_SW128 |
                    (((uint64_t)((sbase + G1_B_OFF + s * G1_B_STAGE) >> 4)) & 0x3FFF);
                if (kt == 0 && j > 0) {
                    mbar_wait(sbase + OFF_EPI0, (uint32_t)((j - 1) & 1));
                    TC_FENCE_AFTER();
                }
                #pragma unroll
                for (int ks = 0; ks < 8; ks++) {
                    uint64_t ko = (uint64_t)((ks >> 2) * 1024 + 2 * (ks & 3));
                    mma_f16_cg2(tmem_base, adesc + ko, bdesc + ko, (uint32_t)(kt | ks));
                }
                if (kt == nk - 1) tc_commit_mc(sbase + OFF_DONE0, (uint16_t)0x3);
                if (kt == 0 && j > 0) {
                    mbar_wait(sbase + OFF_EPI1, (uint32_t)((j - 1) & 1));
                    TC_FENCE_AFTER();
                }
                #pragma unroll
                for (int ks = 0; ks < 8; ks++) {
                    uint64_t ko = (uint64_t)((ks >> 2) * 1024 + 2 * (ks & 3));
                    mma_f16_cg2(tmem_base + 256, adesc + ko, bdesc + 2048 + ko,
                                (uint32_t)(kt | ks));
                }
                tc_commit_mc(sbase + OFF_EMPTY + 8 * s, (uint16_t)0x3);
                if (++s == G1_NST) { s = 0; ph ^= 1; }
            }
            tc_commit_mc(sbase + OFF_DONE1, (uint16_t)0x3);
        }
    } else if (warp >= 4 && warp < 8) {
        const int sub = warp & 3;
        int j = 0;
        for (int t = pair; t < ntiles; t += NPAIRS, j++) {
            const int m = t & (MB - 1), q = t / MB;
            const int nb = (q + (m & nbm1)) & nbm1;
            const size_t row = (size_t)(m * 256 + (int)rank * 128 + sub * 32 + lane);
            const size_t rb  = row * (size_t)Nout + (size_t)nb * G1_TN;
            #pragma unroll
            for (int half = 0; half < 2; half++) {
                mbar_wait(sbase + (half == 0 ? OFF_DONE0 : OFF_DONE1), (uint32_t)(j & 1));
                TC_FENCE_AFTER();
                const int cb = half * 8;
                #pragma unroll
                for (int g = 0; g < 4; g++) {
                    uint32_t rbuf[2][32];
                    ldtm_x32(rbuf[0], tmem_base + 32 * (cb + g * 2));
                    ldtm_x32(rbuf[1], tmem_base + 32 * (cb + g * 2 + 1));
                    TC_WAIT_LD();
                    #pragma unroll
                    for (int k = 0; k < 2; k++) {
                        const uint32_t* r = rbuf[k];
                        __half* dst = Dptr + rb + 32 * (cb + g * 2 + k);
                        uint4 o;
                        #pragma unroll
                        for (int qd = 0; qd < 4; qd++) {
                            o.x = pack_h2(__uint_as_float(r[8 * qd + 0]), __uint_as_float(r[8 * qd + 1]));
                            o.y = pack_h2(__uint_as_float(r[8 * qd + 2]), __uint_as_float(r[8 * qd + 3]));
                            o.z = pack_h2(__uint_as_float(r[8 * qd + 4]), __uint_as_float(r[8 * qd + 5]));
                            o.w = pack_h2(__uint_as_float(r[8 * qd + 6]), __uint_as_float(r[8 * qd + 7]));
                            reinterpret_cast<uint4*>(dst)[qd] = o;
                        }
                    }
                }
                TC_FENCE_BEFORE();
                __syncwarp();
                if (lane == 0)
                    mbar_arrive_rank(sbase + (half == 0 ? OFF_EPI0 : OFF_EPI1), 0u);
            }
        }
    }

    __syncthreads();
    if (warp == 0) {
        asm volatile("tcgen05.dealloc.cta_group::2.sync.aligned.b32 %0, %1;"
                     :: "r"(tmem_base), "r"(512u));
    }
    CLUSTER_SYNC();
#else
    if (tid == 0 && pair == 0) ((__half*)Dptr)[0] = __float2half_rn(Aptr[0]);  // compile-only
#endif
}

// ====== GEMM2 tall: y = T @ W2^T, pair tile 512x256, B shared over 2 M-subtiles ======
__global__ __launch_bounds__(256, 1) __cluster_dims__(2, 1, 1)
void gemm2_tall(const __grid_constant__ CUtensorMap a_map,
                const __grid_constant__ CUtensorMap b_map,
                float* __restrict__ Dptr, int ntiles)
{
    extern __shared__ char smem[];
    const uint32_t sbase = smem_u32(smem);
    const int tid  = threadIdx.x;
    const int warp = tid >> 5;
    const int lane = tid & 31;
    const uint32_t rank = cluster_rank();
    const int pair = blockIdx.x >> 1;
    const int Nout = DOUT, nk = RANK / G2_BK;   // 8

#if TC_PATH
    if (warp == 0) {
        asm volatile("tcgen05.alloc.cta_group::2.sync.aligned.shared::cta.b32 [%0], %1;"
                     :: "r"(sbase + OFF_TMEM), "r"(512u) : "memory");
        asm volatile("tcgen05.relinquish_alloc_permit.cta_group::2.sync.aligned;");
    }
    if (tid == 0) {
        #pragma unroll
        for (int s = 0; s < G2_NST; s++) {
            mbar_init(sbase + OFF_EMPTY + 8 * s, 1);
            mbar_init(sbase + OFF_PFULL + 8 * s, 1);
        }
        mbar_init(sbase + OFF_DONE0, 1);   // per TMEM buffer (M-subtile)
        mbar_init(sbase + OFF_DONE1, 1);
        mbar_init(sbase + OFF_EPI0, 8);
        mbar_init(sbase + OFF_EPI1, 8);
    }
    __syncthreads();
    CLUSTER_SYNC();

    uint32_t tmem_base;
    asm volatile("ld.shared.b32 %0, [%1];" : "=r"(tmem_base) : "r"(sbase + OFF_TMEM));

    if (warp == 1 && lane == 0) {
        // ---- TMA producer: A0 + A1 + B per stage (3 cg2 loads, 96KB/CTA) ----
        int s = 0, ph = 1;
        for (int t = pair; t < ntiles; t += NPAIRS) {
            const int m = t & (G2_MB - 1);
            const int nb = ((t >> 4) + m) & (G2_NB - 1);
            const int bm0 = m * 512 + (int)rank * 128;
            const int bm1 = bm0 + 256;
            const int by  = nb * 256 + (int)rank * 128;
            for (int kt = 0; kt < nk; kt++) {
                mbar_wait(sbase + OFF_EMPTY + 8 * s, (uint32_t)ph);
                const uint32_t pf = sbase + OFF_PFULL + 8 * s;
                if (rank == 0) mbar_expect_tx(pf, 196608u);  // 96KB x 2 CTAs
                const uint32_t sg = sbase + G2_OFF + s * G2_STAGE;
                #pragma unroll
                for (int kh = 0; kh < 2; kh++) {
                    const int x = kt * G2_BK + kh * 64;
                    tma_ld_2d_cg2(sg + kh * 16384,         &a_map, x, bm0, pf);
                    tma_ld_2d_cg2(sg + 32768 + kh * 16384, &a_map, x, bm1, pf);
                    tma_ld_2d_cg2(sg + 65536 + kh * 16384, &b_map, x, by,  pf);
                }
                if (++s == G2_NST) { s = 0; ph ^= 1; }
            }
        }
    } else if (rank == 0 && warp == 0 && lane == 0) {
        // ---- MMA issuer: two dispatch groups per stage into the two TMEM buffers ----
        int s = 0, ph = 0, j = 0;
        for (int t = pair; t < ntiles; t += NPAIRS, j++) {
            for (int kt = 0; kt < nk; kt++) {
                mbar_wait(sbase + OFF_PFULL + 8 * s, (uint32_t)ph);
                const uint32_t sg = sbase + G2_OFF + s * G2_STAGE;
                uint64_t a0 = DESC_BASE_SW128 | (((uint64_t)(sg >> 4)) & 0x3FFF);
                uint64_t a1 = DESC_BASE_SW128 | (((uint64_t)((sg + 32768) >> 4)) & 0x3FFF);
                uint64_t bd = DESC_BASE_SW128 | (((uint64_t)((sg + 65536) >> 4)) & 0x3FFF);
                if (kt == 0 && j > 0) {
                    mbar_wait(sbase + OFF_EPI0, (uint32_t)((j - 1) & 1));
                    TC_FENCE_AFTER();
                }
                #pragma unroll
                for (int ks = 0; ks < 8; ks++) {
                    uint64_t ko = (uint64_t)((ks >> 2) * 1024 + 2 * (ks & 3));
                    mma_f16_cg2(tmem_base, a0 + ko, bd + ko, (uint32_t)(kt | ks));
                }
                if (kt == nk - 1) tc_commit_mc(sbase + OFF_DONE0, (uint16_t)0x3);
                if (kt == 0 && j > 0) {
                    mbar_wait(sbase + OFF_EPI1, (uint32_t)((j - 1) & 1));
                    TC_FENCE_AFTER();
                }
                #pragma unroll
                for (int ks = 0; ks < 8; ks++) {
                    uint64_t ko = (uint64_t)((ks >> 2) * 1024 + 2 * (ks & 3));
                    mma_f16_cg2(tmem_base + 256, a1 + ko, bd + ko, (uint32_t)(kt | ks));
                }
                tc_commit_mc(sbase + OFF_EMPTY + 8 * s, (uint16_t)0x3);
                if (++s == G2_NST) { s = 0; ph ^= 1; }
            }
            tc_commit_mc(sbase + OFF_DONE1, (uint16_t)0x3);
        }
    } else if (warp >= 4 && warp < 8) {
        // ---- epilogue: drain buf0 (rows bm0) then buf1 (rows bm1), batched EG=4 ----
        const int sub = warp & 3;
        int j = 0;
        for (int t = pair; t < ntiles; t += NPAIRS, j++) {
            const int m = t & (G2_MB - 1);
            const int nb = ((t >> 4) + m) & (G2_NB - 1);
            #pragma unroll
            for (int half = 0; half < 2; half++) {
                mbar_wait(sbase + (half == 0 ? OFF_DONE0 : OFF_DONE1), (uint32_t)(j & 1));
                TC_FENCE_AFTER();
                const size_t row = (size_t)(m * 512 + half * 256 + (int)rank * 128
                                            + sub * 32 + lane);
                float* drow = Dptr + row * (size_t)Nout + (size_t)nb * 256;
                const uint32_t btm = tmem_base + (uint32_t)(half * 256);
                #pragma unroll
                for (int g = 0; g < 2; g++) {
                    uint32_t rbuf[4][32];
                    #pragma unroll
                    for (int k = 0; k < 4; k++)
                        ldtm_x32(rbuf[k], btm + 32 * (g * 4 + k));
                    TC_WAIT_LD();
                    #pragma unroll
                    for (int k = 0; k < 4; k++) {
                        const uint32_t* r = rbuf[k];
                        float* dst = drow + 32 * (g * 4 + k);
                        #pragma unroll
                        for (int qd = 0; qd < 8; qd++)
                            reinterpret_cast<float4*>(dst)[qd] =
                                make_float4(__uint_as_float(r[4 * qd + 0]),
                                            __uint_as_float(r[4 * qd + 1]),
                                            __uint_as_float(r[4 * qd + 2]),
                                            __uint_as_float(r[4 * qd + 3]));
                    }
                }
                TC_FENCE_BEFORE();
                __syncwarp();
                if (lane == 0)
                    mbar_arrive_rank(sbase + (half == 0 ? OFF_EPI0 : OFF_EPI1), 0u);
            }
        }
    }

    __syncthreads();
    if (warp == 0) {
        asm volatile("tcgen05.dealloc.cta_group::2.sync.aligned.b32 %0, %1;"
                     :: "r"(tmem_base), "r"(512u));
    }
    CLUSTER_SYNC();
#else
    if (tid == 0 && pair == 0) Dptr[0] = 0.f;   // compile-only
#endif
}

// ---------------- host: tensormap construction ----------------
typedef CUresult (*EncodeTiledFn)(
    CUtensorMap*, CUtensorMapDataType, cuuint32_t, void*,
    const cuuint64_t*, const cuuint64_t*, const cuuint32_t*, const cuuint32_t*,
    CUtensorMapInterleave, CUtensorMapSwizzle, CUtensorMapL2promotion, CUtensorMapFloatOOBfill);

static void make_map_f16(EncodeTiledFn fn, CUtensorMap* m, const void* ptr,
                         uint64_t kdim, uint64_t rows) {
    cuuint64_t dims[2]    = {kdim, rows};
    cuuint64_t strides[1] = {kdim * 2};
    cuuint32_t box[2]     = {64, 128};       // 64 fp16 = 128B x 128 rows (SW128)
    cuuint32_t es[2]      = {1, 1};
    fn(m, CU_TENSOR_MAP_DATA_TYPE_FLOAT16, 2, const_cast<void*>(ptr),
       dims, strides, box, es,
       CU_TENSOR_MAP_INTERLEAVE_NONE, CU_TENSOR_MAP_SWIZZLE_128B,
       CU_TENSOR_MAP_L2_PROMOTION_L2_128B, CU_TENSOR_MAP_FLOAT_OOB_FILL_NONE);
}

extern "C" void kernel_launch(void* const* d_in, const int* in_sizes, int n_in,
                              void* d_out, int out_size)
{
    const float* x  = (const float*)d_in[0];   // [8192, 4096]
    const float* U  = (const float*)d_in[1];   // [4096, 1024]
    const float* S  = (const float*)d_in[2];   // [1024]
    const float* Vh = (const float*)d_in[3];   // [1024, 4096]
    float* y = (float*)d_out;                  // [8192, 4096]

    __half *W1, *W2, *T;
    cudaGetSymbolAddress((void**)&W1, g_W1);
    cudaGetSymbolAddress((void**)&W2, g_W2);
    cudaGetSymbolAddress((void**)&T,  g_T);

    void* sym = nullptr;
    cudaDriverEntryPointQueryResult qres;
    cudaGetDriverEntryPointByVersion("cuTensorMapEncodeTiled", &sym, 12000,
                                     cudaEnableDefault, &qres);
    EncodeTiledFn enc = (EncodeTiledFn)sym;

    CUtensorMap mapT{}, mapW1{}, mapW2{};
    make_map_f16(enc, &mapT,  T,  RANK, M_TOT);   // GEMM2 A
    make_map_f16(enc, &mapW1, W1, DIN,  RANK);    // GEMM1 B
    make_map_f16(enc, &mapW2, W2, RANK, DOUT);    // GEMM2 B

    cudaFuncSetAttribute((const void*)gemm1_f16,
                         cudaFuncAttributeMaxDynamicSharedMemorySize, G1_SMEM);
    cudaFuncSetAttribute((const void*)gemm2_tall,
                         cudaFuncAttributeMaxDynamicSharedMemorySize, G2_SMEM);

    // prepass: W1 = f16(S*Vh), W2 = f16(U)   (x -> f16 fused into GEMM1 A-producers)
    prep_scale_half<<<dim3(DIN / 4 / 256, RANK), 256>>>(Vh, S, W1, DIN / 4);
    prep_half<<<512, 256>>>(U, W2, (DOUT * RANK) / 4);

    // GEMM 1: T[8192,1024] = f16(x) @ W1^T   (64 tiles of 256x512)
    gemm1_f16<<<GRID_CTAS, 512, G1_SMEM>>>(x, mapW1, T, MB * (RANK / G1_TN));
    // GEMM 2: y[8192,4096] = T @ W2^T        (256 tall tiles of 512x256)
    gemm2_tall<<<GRID_CTAS, 256, G2_SMEM>>>(mapT, mapW2, y, G2_MB * G2_NB);
}

// round 14
// speedup vs baseline: 1.1842x; 1.1842x over previous
#include <cuda_runtime.h>
#include <cuda.h>
#include <cuda_fp16.h>
#include <cstdint>
#include <cstddef>

// ---------------- problem constants ----------------
#define M_TOT 8192
#define DIN   4096
#define DOUT  4096
#define RANK  1024

#define NPAIRS 74
#define GRID_CTAS 148
#define MB 32                  // M_TOT / 256

// ===== GEMM1 layout: pair tile 256x512, BK=128, NSTAGE=2 =====
#define G1_TN 512
#define G1_BK 128
#define G1_NST 2
#define G1_A_STAGE 32768
#define G1_B_STAGE 65536
#define G1_A_OFF 1024
#define G1_B_OFF (G1_A_OFF + G1_NST * G1_A_STAGE)          // 66560
#define G1_SMEM  (G1_B_OFF + G1_NST * G1_B_STAGE)          // 197632

// ===== GEMM2 layout (R12-proven, double-buffered TMEM): 256x256, BK=128, NSTAGE=3 =====
#define G2_TN 256
#define G2_BK 128
#define G2_NST 3
#define G2_A_STAGE 32768
#define G2_B_STAGE 32768
#define G2_A_OFF 1024
#define G2_B_OFF (G2_A_OFF + G2_NST * G2_A_STAGE)          // 99328
#define G2_SMEM  (G2_B_OFF + G2_NST * G2_B_STAGE)          // 197632

// control block (first 1KB of smem)
#define OFF_TMEM   0
#define OFF_EMPTY  16
#define OFF_PFULL  48
#define OFF_DONE0  80
#define OFF_DONE1  88
#define OFF_EPI0   96
#define OFF_EPI1   104

// idesc: kind::f16, D=f32(bit4), A=F16(0), B=F16(0), N=256, M=256 (cg2)
#define IDESC_F16_CG2 ((1u << 4) | ((256u / 8u) << 17) | ((256u / 16u) << 24))

#define DESC_BASE_SW128 \
    ((uint64_t(2) << 61) | (uint64_t(1) << 46) | (uint64_t(64) << 32) | (uint64_t(1) << 16))

#if defined(__CUDA_ARCH__) && (defined(__CUDA_ARCH_FEAT_SM103_ALL) || defined(__CUDA_ARCH_FEAT_SM100_ALL) || defined(__CUDA_ARCH_FEAT_SM101_ALL))
#define TC_PATH 1
#else
#define TC_PATH 0
#endif

// ---------------- scratch (allocation-free) ----------------
__device__ __align__(16) __half g_W1[(size_t)RANK  * DIN];
__device__ __align__(16) __half g_W2[(size_t)DOUT  * RANK];
__device__ __align__(16) __half g_T [(size_t)M_TOT * RANK];

// ---------------- helpers ----------------
__device__ __forceinline__ uint32_t pack_h2(float lo, float hi) {
    __half2 h = __floats2half2_rn(lo, hi);
    return *reinterpret_cast<uint32_t*>(&h);
}
__device__ __forceinline__ uint32_t smem_u32(const void* p) {
    uint32_t a;
    asm("{ .reg .u64 t; cvta.to.shared.u64 t, %1; cvt.u32.u64 %0, t; }" : "=r"(a) : "l"(p));
    return a;
}
__device__ __forceinline__ uint32_t sw128(uint32_t o) { return o ^ ((o >> 3) & 0x70); }
__device__ __forceinline__ uint32_t cluster_rank() {
    uint32_t r;
    asm("mov.u32 %0, %%cluster_ctarank;" : "=r"(r));
    return r;
}

#if TC_PATH
__device__ __forceinline__ void mbar_init(uint32_t a, uint32_t cnt) {
    asm volatile("mbarrier.init.shared.b64 [%0], %1;" :: "r"(a), "r"(cnt) : "memory");
}
__device__ __forceinline__ void mbar_arrive_rank(uint32_t a, uint32_t rank) {
    asm volatile(
        "{\n\t"
        ".reg .b32 r;\n\t"
        "mapa.shared::cluster.u32 r, %0, %1;\n\t"
        "mbarrier.arrive.shared::cluster.b64 _, [r];\n\t"
        "}" :: "r"(a), "r"(rank) : "memory");
}
__device__ __forceinline__ void mbar_expect_tx(uint32_t a, uint32_t bytes) {
    asm volatile("mbarrier.arrive.expect_tx.shared.b64 _, [%0], %1;"
                 :: "r"(a), "r"(bytes) : "memory");
}
__device__ __forceinline__ void mbar_wait(uint32_t a, uint32_t parity) {
    asm volatile(
        "{\n\t"
        ".reg .pred P;\n\t"
        "W_%=:\n\t"
        "mbarrier.try_wait.parity.acquire.cluster.shared::cta.b64 P, [%0], %1, 0x989680;\n\t"
        "@!P bra.uni W_%=;\n\t"
        "}" :: "r"(a), "r"(parity) : "memory");
}
// cta_group::2 TMA: data to LOCAL smem, complete_tx to the PAIR LEADER's barrier.
__device__ __forceinline__ void tma_ld_2d_cg2(uint32_t dst, const CUtensorMap* m,
                                              int x, int y, uint32_t bar) {
    asm volatile(
        "{\n\t"
        ".reg .b32 lb;\n\t"
        "and.b32 lb, %4, 0xFEFFFFFF;\n\t"
        "cp.async.bulk.tensor.2d.cta_group::2.shared::cluster.global"
        ".tile.mbarrier::complete_tx::bytes [%0], [%1, {%2, %3}], [lb];\n\t"
        "}"
        :: "r"(dst), "l"(m), "r"(x), "r"(y), "r"(bar) : "memory");
}
__device__ __forceinline__ void mma_f16_cg2(uint32_t d_tmem, uint64_t a_desc, uint64_t b_desc,
                                            uint32_t enable_d) {
    asm volatile(
        "{\n\t"
        ".reg .pred p;\n\t"
        "setp.ne.u32 p, %4, 0;\n\t"
        "tcgen05.mma.cta_group::2.kind::f16 [%0], %1, %2, %3, "
        "{%5,%5,%5,%5,%5,%5,%5,%5}, p;\n\t"
        "}"
        :: "r"(d_tmem), "l"(a_desc), "l"(b_desc), "r"(IDESC_F16_CG2), "r"(enable_d), "r"(0u)
        : "memory");
}
__device__ __forceinline__ void tc_commit_mc(uint32_t mbar, uint16_t mask) {
    asm volatile(
        "tcgen05.commit.cta_group::2.mbarrier::arrive::one.shared::cluster.multicast::cluster.b64 [%0], %1;"
        :: "r"(mbar), "h"(mask) : "memory");
}
__device__ __forceinline__ void ldtm_x32(uint32_t* r, uint32_t addr) {
    asm volatile(
        "tcgen05.ld.sync.aligned.32x32b.x32.b32 "
        "{%0, %1, %2, %3, %4, %5, %6, %7, "
        " %8, %9, %10, %11, %12, %13, %14, %15, "
        " %16, %17, %18, %19, %20, %21, %22, %23, "
        " %24, %25, %26, %27, %28, %29, %30, %31}, [%32];"
        : "=r"(r[0]),  "=r"(r[1]),  "=r"(r[2]),  "=r"(r[3]),
          "=r"(r[4]),  "=r"(r[5]),  "=r"(r[6]),  "=r"(r[7]),
          "=r"(r[8]),  "=r"(r[9]),  "=r"(r[10]), "=r"(r[11]),
          "=r"(r[12]), "=r"(r[13]), "=r"(r[14]), "=r"(r[15]),
          "=r"(r[16]), "=r"(r[17]), "=r"(r[18]), "=r"(r[19]),
          "=r"(r[20]), "=r"(r[21]), "=r"(r[22]), "=r"(r[23]),
          "=r"(r[24]), "=r"(r[25]), "=r"(r[26]), "=r"(r[27]),
          "=r"(r[28]), "=r"(r[29]), "=r"(r[30]), "=r"(r[31])
        : "r"(addr));
}
#define TC_WAIT_LD() asm volatile("tcgen05.wait::ld.sync.aligned;" ::: "memory")
#define TC_FENCE_AFTER()  asm volatile("tcgen05.fence::after_thread_sync;" ::: "memory")
#define TC_FENCE_BEFORE() asm volatile("tcgen05.fence::before_thread_sync;" ::: "memory")
#define CLUSTER_SYNC() do { \
    asm volatile("barrier.cluster.arrive.aligned;" ::: "memory"); \
    asm volatile("barrier.cluster.wait.aligned;" ::: "memory"); \
} while (0)
#endif  // TC_PATH

// ---------------- prepass kernel: W1 = f16(S * Vh) ----------------
__global__ void prep_scale_half(const float* __restrict__ Vh, const float* __restrict__ S,
                                __half* __restrict__ out, int cols4) {
    int r = blockIdx.y;
    float s = __ldg(S + r);
    int c = blockIdx.x * blockDim.x + threadIdx.x;
    if (c < cols4) {
        float4 v = reinterpret_cast<const float4*>(Vh + (size_t)r * (cols4 * 4))[c];
        uint2 o;
        o.x = pack_h2(v.x * s, v.y * s);
        o.y = pack_h2(v.z * s, v.w * s);
        reinterpret_cast<uint2*>(out + (size_t)r * (cols4 * 4))[c] = o;
    }
}

// ================= GEMM1: T = f16(x) @ W1^T (fused rounding, LDG prefetch) ============
// Idle pairs (pair >= ntiles) convert U -> f16(W2) for GEMM2 concurrently.
__global__ __launch_bounds__(512, 1) __cluster_dims__(2, 1, 1)
void gemm1_f16(const float* __restrict__ Aptr,
               const __grid_constant__ CUtensorMap b_map,
               __half* __restrict__ Dptr, int ntiles,
               const float* __restrict__ Uptr, __half* __restrict__ W2ptr, int w2n4)
{
    extern __shared__ char smem[];
    const uint32_t sbase = smem_u32(smem);
    const int tid  = threadIdx.x;
    const int warp = tid >> 5;
    const int lane = tid & 31;
    const uint32_t rank = cluster_rank();
    const int pair = blockIdx.x >> 1;
    const int K = DIN, Nout = RANK, nk = DIN / G1_BK, nbm1 = (RANK / G1_TN) - 1;

#if TC_PATH
    if (warp == 0) {
        asm volatile("tcgen05.alloc.cta_group::2.sync.aligned.shared::cta.b32 [%0], %1;"
                     :: "r"(sbase + OFF_TMEM), "r"(512u) : "memory");
        asm volatile("tcgen05.relinquish_alloc_permit.cta_group::2.sync.aligned;");
    }
    if (tid == 0) {
        #pragma unroll
        for (int s = 0; s < G1_NST; s++) {
            mbar_init(sbase + OFF_EMPTY + 8 * s, 1);
            mbar_init(sbase + OFF_PFULL + 8 * s, 17u);
        }
        mbar_init(sbase + OFF_DONE0, 1);
        mbar_init(sbase + OFF_DONE1, 1);
        mbar_init(sbase + OFF_EPI0, 8);
        mbar_init(sbase + OFF_EPI1, 8);
    }
    __syncthreads();
    CLUSTER_SYNC();

    uint32_t tmem_base;
    asm volatile("ld.shared.b32 %0, [%1];" : "=r"(tmem_base) : "r"(sbase + OFF_TMEM));

    if (pair >= ntiles) {
        // ============ idle pairs: convert U -> f16(W2) for GEMM2 ============
        const int nidle = (GRID_CTAS / 2) - ntiles;            // 10 pairs = 20 CTAs
        const int base = ((blockIdx.x - 2 * ntiles) * 512) + tid;
        const int stride = nidle * 2 * 512;
        for (int i = base; i < w2n4; i += stride) {
            float4 v = __ldg(reinterpret_cast<const float4*>(Uptr) + i);
            uint2 o;
            o.x = pack_h2(v.x, v.y);
            o.y = pack_h2(v.z, v.w);
            reinterpret_cast<uint2*>(W2ptr)[i] = o;
        }
    } else if (warp == 1 && lane == 0) {
        // ============ TMA producer (B only) ============
        int s = 0, ph = 1;
        const int m = pair & (MB - 1), q = pair / MB;
        const int nb = (q + (m & nbm1)) & nbm1;
        const int bn = nb * G1_TN;
        for (int kt = 0; kt < nk; kt++) {
            mbar_wait(sbase + OFF_EMPTY + 8 * s, (uint32_t)ph);
            const uint32_t pf = sbase + OFF_PFULL + 8 * s;
            if (rank == 0) mbar_expect_tx(pf, 131072u);
            const uint32_t sB = sbase + G1_B_OFF + s * G1_B_STAGE;
            #pragma unroll
            for (int kh = 0; kh < 2; kh++) {
                const int x = kt * G1_BK + kh * 64;
                tma_ld_2d_cg2(sB + kh * 16384,         &b_map, x, bn + (int)rank * 128, pf);
                tma_ld_2d_cg2(sB + 32768 + kh * 16384, &b_map, x, bn + 256 + (int)rank * 128, pf);
            }
            if (++s == G1_NST) { s = 0; ph ^= 1; }
        }
    } else if (warp >= 8) {
        // ============ A producers with LDG prefetch: warps 8-15 ============
        const int pt = tid - 256;
        const int m = pair & (MB - 1);
        const int bm_cta = m * 256 + (int)rank * 128;
        const float* Agb = Aptr + (size_t)bm_cta * K;
        const int r0 = pt >> 4, g0 = pt & 15;   // per-thread row/granule base

        float4 P[8], W[8];
        // prologue: prefetch kt = 0
        {
            const float* Ag = Agb;
            #pragma unroll
            for (int i = 0; i < 8; i++) {
                const float* src = Ag + (size_t)(r0 + 16 * i) * K + g0 * 8;
                P[i] = __ldg(reinterpret_cast<const float4*>(src));
                W[i] = __ldg(reinterpret_cast<const float4*>(src + 4));
            }
        }
        int s = 0, ph = 1;
        for (int kt = 0; kt < nk; kt++) {
            mbar_wait(sbase + OFF_EMPTY + 8 * s, (uint32_t)ph);
            #pragma unroll
            for (int i = 0; i < 8; i++) {
                const int r = r0 + 16 * i;
                uint4 h;
                h.x = pack_h2(P[i].x, P[i].y);
                h.y = pack_h2(P[i].z, P[i].w);
                h.z = pack_h2(W[i].x, W[i].y);
                h.w = pack_h2(W[i].z, W[i].w);
                uint32_t off = (uint32_t)((g0 >> 3) * 16384) +
                               sw128((uint32_t)(r * 128 + (g0 & 7) * 16));
                *reinterpret_cast<uint4*>(smem + G1_A_OFF + s * G1_A_STAGE + off) = h;
            }
            asm volatile("fence.proxy.async;" ::: "memory");
            __syncwarp();
            if (lane == 0) mbar_arrive_rank(sbase + OFF_PFULL + 8 * s, 0u);
            if (kt + 1 < nk) {   // prefetch next stage while MMA consumes this one
                const float* Ag = Agb + (size_t)(kt + 1) * G1_BK;
                #pragma unroll
                for (int i = 0; i < 8; i++) {
                    const float* src = Ag + (size_t)(r0 + 16 * i) * K + g0 * 8;
                    P[i] = __ldg(reinterpret_cast<const float4*>(src));
                    W[i] = __ldg(reinterpret_cast<const float4*>(src + 4));
                }
            }
            if (++s == G1_NST) { s = 0; ph ^= 1; }
        }
    } else if (rank == 0 && warp == 0 && lane == 0) {
        // ============ MMA issuer ============
        int s = 0, ph = 0;
        for (int kt = 0; kt < nk; kt++) {
            mbar_wait(sbase + OFF_PFULL + 8 * s, (uint32_t)ph);
            uint64_t adesc = DESC_BASE_SW128 |
                (((uint64_t)((sbase + G1_A_OFF + s * G1_A_STAGE) >> 4)) & 0x3FFF);
            uint64_t bdesc = DESC_BASE_SW128 |
                (((uint64_t)((sbase + G1_B_OFF + s * G1_B_STAGE) >> 4)) & 0x3FFF);
            #pragma unroll
            for (int ks = 0; ks < 8; ks++) {
                uint64_t ko = (uint64_t)((ks >> 2) * 1024 + 2 * (ks & 3));
                mma_f16_cg2(tmem_base, adesc + ko, bdesc + ko, (uint32_t)(kt | ks));
            }
            if (kt == nk - 1) tc_commit_mc(sbase + OFF_DONE0, (uint16_t)0x3);
            #pragma unroll
            for (int ks = 0; ks < 8; ks++) {
                uint64_t ko = (uint64_t)((ks >> 2) * 1024 + 2 * (ks & 3));
                mma_f16_cg2(tmem_base + 256, adesc + ko, bdesc + 2048 + ko,
                            (uint32_t)(kt | ks));
            }
            tc_commit_mc(sbase + OFF_EMPTY + 8 * s, (uint16_t)0x3);
            if (++s == G1_NST) { s = 0; ph ^= 1; }
        }
        tc_commit_mc(sbase + OFF_DONE1, (uint16_t)0x3);
    } else if (warp >= 4 && warp < 8) {
        // ============ epilogue: fp16 out, batched LDTM (EG=2) ============
        const int sub = warp & 3;
        const int m = pair & (MB - 1), q = pair / MB;
        const int nb = (q + (m & nbm1)) & nbm1;
        const size_t row = (size_t)(m * 256 + (int)rank * 128 + sub * 32 + lane);
        const size_t rb  = row * (size_t)Nout + (size_t)nb * G1_TN;
        #pragma unroll
        for (int half = 0; half < 2; half++) {
            mbar_wait(sbase + (half == 0 ? OFF_DONE0 : OFF_DONE1), 0u);
            TC_FENCE_AFTER();
            const int cb = half * 8;
            #pragma unroll
            for (int g = 0; g < 4; g++) {
                uint32_t rbuf[2][32];
                ldtm_x32(rbuf[0], tmem_base + 32 * (cb + g * 2));
                ldtm_x32(rbuf[1], tmem_base + 32 * (cb + g * 2 + 1));
                TC_WAIT_LD();
                #pragma unroll
                for (int k = 0; k < 2; k++) {
                    const uint32_t* r = rbuf[k];
                    __half* dst = Dptr + rb + 32 * (cb + g * 2 + k);
                    uint4 o;
                    #pragma unroll
                    for (int qd = 0; qd < 4; qd++) {
                        o.x = pack_h2(__uint_as_float(r[8 * qd + 0]), __uint_as_float(r[8 * qd + 1]));
                        o.y = pack_h2(__uint_as_float(r[8 * qd + 2]), __uint_as_float(r[8 * qd + 3]));
                        o.z = pack_h2(__uint_as_float(r[8 * qd + 4]), __uint_as_float(r[8 * qd + 5]));
                        o.w = pack_h2(__uint_as_float(r[8 * qd + 6]), __uint_as_float(r[8 * qd + 7]));
                        reinterpret_cast<uint4*>(dst)[qd] = o;
                    }
                }
            }
            TC_FENCE_BEFORE();
        }
    }

    __syncthreads();
    if (warp == 0) {
        asm volatile("tcgen05.dealloc.cta_group::2.sync.aligned.b32 %0, %1;"
                     :: "r"(tmem_base), "r"(512u));
    }
    CLUSTER_SYNC();
#else
    if (tid == 0 && pair == 0) ((__half*)Dptr)[0] = __float2half_rn(Aptr[0]);  // compile-only
#endif
}

// ================= GEMM2 (R12-exact): y = T @ W2^T, TMEM double-buffered ================
__global__ __launch_bounds__(256, 1) __cluster_dims__(2, 1, 1)
void gemm2_db(const __grid_constant__ CUtensorMap a_map,
              const __grid_constant__ CUtensorMap b_map,
              float* __restrict__ Dptr, int ntiles)
{
    extern __shared__ char smem[];
    const uint32_t sbase = smem_u32(smem);
    const int tid  = threadIdx.x;
    const int warp = tid >> 5;
    const int lane = tid & 31;
    const uint32_t rank = cluster_rank();
    const int pair = blockIdx.x >> 1;
    const int Nout = DOUT, nk = RANK / G2_BK;   // 8
    const int nbm1 = (DOUT / G2_TN) - 1;        // 15

#if TC_PATH
    if (warp == 0) {
        asm volatile("tcgen05.alloc.cta_group::2.sync.aligned.shared::cta.b32 [%0], %1;"
                     :: "r"(sbase + OFF_TMEM), "r"(512u) : "memory");
        asm volatile("tcgen05.relinquish_alloc_permit.cta_group::2.sync.aligned;");
    }
    if (tid == 0) {
        #pragma unroll
        for (int s = 0; s < G2_NST; s++) {
            mbar_init(sbase + OFF_EMPTY + 8 * s, 1);
            mbar_init(sbase + OFF_PFULL + 8 * s, 1);
        }
        mbar_init(sbase + OFF_DONE0, 1);
        mbar_init(sbase + OFF_DONE1, 1);
        mbar_init(sbase + OFF_EPI0, 8);
        mbar_init(sbase + OFF_EPI1, 8);
    }
    __syncthreads();
    CLUSTER_SYNC();

    uint32_t tmem_base;
    asm volatile("ld.shared.b32 %0, [%1];" : "=r"(tmem_base) : "r"(sbase + OFF_TMEM));

    if (warp == 1 && lane == 0) {
        int s = 0, ph = 1;
        for (int t = pair; t < ntiles; t += NPAIRS) {
            const int m = t & (MB - 1), q = t / MB;
            const int nb = (q + (m & nbm1)) & nbm1;
            const int bm_cta = m * 256 + (int)rank * 128;
            const int bn = nb * G2_TN;
            for (int kt = 0; kt < nk; kt++) {
                mbar_wait(sbase + OFF_EMPTY + 8 * s, (uint32_t)ph);
                const uint32_t pf = sbase + OFF_PFULL + 8 * s;
                if (rank == 0) mbar_expect_tx(pf, 131072u);
                const uint32_t sA = sbase + G2_A_OFF + s * G2_A_STAGE;
                const uint32_t sB = sbase + G2_B_OFF + s * G2_B_STAGE;
                #pragma unroll
                for (int kh = 0; kh < 2; kh++) {
                    const int x = kt * G2_BK + kh * 64;
                    tma_ld_2d_cg2(sA + kh * 16384, &a_map, x, bm_cta, pf);
                    tma_ld_2d_cg2(sB + kh * 16384, &b_map, x, bn + (int)rank * 128, pf);
                }
                if (++s == G2_NST) { s = 0; ph ^= 1; }
            }
        }
    } else if (rank == 0 && warp == 0 && lane == 0) {
        int s = 0, ph = 0, j = 0;
        for (int t = pair; t < ntiles; t += NPAIRS, j++) {
            const int b = j & 1, n = j >> 1;
            const uint32_t dtm = tmem_base + (uint32_t)(b * 256);
            if (n >= 1) {
                mbar_wait(sbase + (b == 0 ? OFF_EPI0 : OFF_EPI1), (uint32_t)((n - 1) & 1));
                TC_FENCE_AFTER();
            }
            for (int kt = 0; kt < nk; kt++) {
                mbar_wait(sbase + OFF_PFULL + 8 * s, (uint32_t)ph);
                uint64_t adesc = DESC_BASE_SW128 |
                    (((uint64_t)((sbase + G2_A_OFF + s * G2_A_STAGE) >> 4)) & 0x3FFF);
                uint64_t bdesc = DESC_BASE_SW128 |
                    (((uint64_t)((sbase + G2_B_OFF + s * G2_B_STAGE) >> 4)) & 0x3FFF);
                #pragma unroll
                for (int ks = 0; ks < 8; ks++) {
                    uint64_t ko = (uint64_t)((ks >> 2) * 1024 + 2 * (ks & 3));
                    mma_f16_cg2(dtm, adesc + ko, bdesc + ko, (uint32_t)(kt | ks));
                }
                tc_commit_mc(sbase + OFF_EMPTY + 8 * s, (uint16_t)0x3);
                if (++s == G2_NST) { s = 0; ph ^= 1; }
            }
            tc_commit_mc(sbase + (b == 0 ? OFF_DONE0 : OFF_DONE1), (uint16_t)0x3);
        }
    } else if (warp >= 4 && warp < 8) {
        const int sub = warp & 3;
        int j = 0;
        for (int t = pair; t < ntiles; t += NPAIRS, j++) {
            const int b = j & 1, n = j >> 1;
            mbar_wait(sbase + (b == 0 ? OFF_DONE0 : OFF_DONE1), (uint32_t)(n & 1));
            TC_FENCE_AFTER();

            const int m = t & (MB - 1), q = t / MB;
            const int nb = (q + (m & nbm1)) & nbm1;
            const size_t row = (size_t)(m * 256 + (int)rank * 128 + sub * 32 + lane);
            float* drow = Dptr + row * (size_t)Nout + (size_t)nb * G2_TN;
            const uint32_t btm = tmem_base + (uint32_t)(b * 256);

            #pragma unroll
            for (int g = 0; g < 2; g++) {
                uint32_t rbuf[4][32];
                #pragma unroll
                for (int k = 0; k < 4; k++)
                    ldtm_x32(rbuf[k], btm + 32 * (g * 4 + k));
                TC_WAIT_LD();
                #pragma unroll
                for (int k = 0; k < 4; k++) {
                    const uint32_t* r = rbuf[k];
                    float* dst = drow + 32 * (g * 4 + k);
                    #pragma unroll
                    for (int qd = 0; qd < 8; qd++)
                        reinterpret_cast<float4*>(dst)[qd] =
                            make_float4(__uint_as_float(r[4 * qd + 0]),
                                        __uint_as_float(r[4 * qd + 1]),
                                        __uint_as_float(r[4 * qd + 2]),
                                        __uint_as_float(r[4 * qd + 3]));
                }
            }
            TC_FENCE_BEFORE();
            __syncwarp();
            if (lane == 0)
                mbar_arrive_rank(sbase + (b == 0 ? OFF_EPI0 : OFF_EPI1), 0u);
        }
    }

    __syncthreads();
    if (warp == 0) {
        asm volatile("tcgen05.dealloc.cta_group::2.sync.aligned.b32 %0, %1;"
                     :: "r"(tmem_base), "r"(512u));
    }
    CLUSTER_SYNC();
#else
    if (tid == 0 && pair == 0) Dptr[0] = 0.f;   // compile-only
#endif
}

// ---------------- host: tensormap construction ----------------
typedef CUresult (*EncodeTiledFn)(
    CUtensorMap*, CUtensorMapDataType, cuuint32_t, void*,
    const cuuint64_t*, const cuuint64_t*, const cuuint32_t*, const cuuint32_t*,
    CUtensorMapInterleave, CUtensorMapSwizzle, CUtensorMapL2promotion, CUtensorMapFloatOOBfill);

static void make_map_f16(EncodeTiledFn fn, CUtensorMap* m, const void* ptr,
                         uint64_t kdim, uint64_t rows) {
    cuuint64_t dims[2]    = {kdim, rows};
    cuuint64_t strides[1] = {kdim * 2};
    cuuint32_t box[2]     = {64, 128};
    cuuint32_t es[2]      = {1, 1};
    fn(m, CU_TENSOR_MAP_DATA_TYPE_FLOAT16, 2, const_cast<void*>(ptr),
       dims, strides, box, es,
       CU_TENSOR_MAP_INTERLEAVE_NONE, CU_TENSOR_MAP_SWIZZLE_128B,
       CU_TENSOR_MAP_L2_PROMOTION_L2_128B, CU_TENSOR_MAP_FLOAT_OOB_FILL_NONE);
}

extern "C" void kernel_launch(void* const* d_in, const int* in_sizes, int n_in,
                              void* d_out, int out_size)
{
    const float* x  = (const float*)d_in[0];   // [8192, 4096]
    const float* U  = (const float*)d_in[1];   // [4096, 1024]
    const float* S  = (const float*)d_in[2];   // [1024]
    const float* Vh = (const float*)d_in[3];   // [1024, 4096]
    float* y = (float*)d_out;                  // [8192, 4096]

    __half *W1, *W2, *T;
    cudaGetSymbolAddress((void**)&W1, g_W1);
    cudaGetSymbolAddress((void**)&W2, g_W2);
    cudaGetSymbolAddress((void**)&T,  g_T);

    void* sym = nullptr;
    cudaDriverEntryPointQueryResult qres;
    cudaGetDriverEntryPointByVersion("cuTensorMapEncodeTiled", &sym, 12000,
                                     cudaEnableDefault, &qres);
    EncodeTiledFn enc = (EncodeTiledFn)sym;

    CUtensorMap mapT{}, mapW1{}, mapW2{};
    make_map_f16(enc, &mapT,  T,  RANK, M_TOT);   // GEMM2 A
    make_map_f16(enc, &mapW1, W1, DIN,  RANK);    // GEMM1 B
    make_map_f16(enc, &mapW2, W2, RANK, DOUT);    // GEMM2 B

    cudaFuncSetAttribute((const void*)gemm1_f16,
                         cudaFuncAttributeMaxDynamicSharedMemorySize, G1_SMEM);
    cudaFuncSetAttribute((const void*)gemm2_db,
                         cudaFuncAttributeMaxDynamicSharedMemorySize, G2_SMEM);

    // prepass: W1 = f16(S*Vh)  (x->f16 fused into GEMM1; U->W2 fused into GEMM1's idle pairs)
    prep_scale_half<<<dim3(DIN / 4 / 256, RANK), 256>>>(Vh, S, W1, DIN / 4);

    // GEMM 1: T[8192,1024] = f16(x) @ W1^T   (64 tiles of 256x512; idle pairs convert W2)
    gemm1_f16<<<GRID_CTAS, 512, G1_SMEM>>>(x, mapW1, T, MB * (RANK / G1_TN),
                                           U, W2, (DOUT * RANK) / 4);
    // GEMM 2: y[8192,4096] = T @ W2^T        (512 tiles of 256x256, TMEM double-buffered)
    gemm2_db<<<GRID_CTAS, 256, G2_SMEM>>>(mapT, mapW2, y, MB * (DOUT / G2_TN));
}